// round 5
// baseline (speedup 1.0000x reference)
#include <cuda_runtime.h>
#include <cuda_bf16.h>
#include <cstdint>

// Problem constants
#define BB   4
#define SS   2048
#define HH   16
#define DH   64
#define DM   1024
#define BHT  (BB*HH)          // 64

// Scratch (device globals: allocation-free)
__device__ float g_qh [(size_t)BB*HH*SS*DH];   // [B,H,S,Dh]
__device__ float g_kh [(size_t)BB*HH*SS*DH];
__device__ float g_vh [(size_t)BB*HH*SS*DH];
__device__ float g_ctx[(size_t)BB*HH*SS*DH];

// fp32 -> tf32 round-to-nearest
__device__ __forceinline__ uint32_t tf32c(float x) {
    uint32_t u;
    asm("cvt.rna.tf32.f32 %0, %1;" : "=r"(u) : "f"(x));
    return u;
}

// m16n8k8 tf32 MMA, fp32 accumulate
__device__ __forceinline__ void mma8(float c[4], const uint32_t a[4], const uint32_t b[2]) {
    asm volatile(
        "mma.sync.aligned.m16n8k8.row.col.f32.tf32.tf32.f32 "
        "{%0,%1,%2,%3},{%4,%5,%6,%7},{%8,%9},{%0,%1,%2,%3};"
        : "+f"(c[0]), "+f"(c[1]), "+f"(c[2]), "+f"(c[3])
        : "r"(a[0]), "r"(a[1]), "r"(a[2]), "r"(a[3]), "r"(b[0]), "r"(b[1]));
}

// FMA-only exp
__device__ __forceinline__ float fexp(float x) {
    float y = x * 1.4426950408889634f;
    float r = rintf(y);
    float c = (y - r) * 0.6931471805599453f;
    float p = 1.3888889e-3f;
    p = fmaf(p, c, 8.3333333e-3f);
    p = fmaf(p, c, 4.1666667e-2f);
    p = fmaf(p, c, 1.6666667e-1f);
    p = fmaf(p, c, 0.5f);
    p = fmaf(p, c, 1.0f);
    p = fmaf(p, c, 1.0f);
    return p * __int_as_float(((int)r + 127) << 23);
}

// ---------------------------------------------------------------------------
// K1: fused QKV projection. 256x128 CTA tile, 8 warps (4m x 2n), warp 64x64.
// BK=16, register-prefetch double buffering.
// ---------------------------------------------------------------------------
__global__ __launch_bounds__(256) void k_qkv_proj(
    const float* __restrict__ xq, const float* __restrict__ xk, const float* __restrict__ xv,
    const float* __restrict__ wq, const float* __restrict__ wk, const float* __restrict__ wv,
    const float* __restrict__ bq, const float* __restrict__ bk, const float* __restrict__ bv)
{
    __shared__ uint32_t As[256*20];
    __shared__ uint32_t Bs[128*20];
    int z = blockIdx.z;
    const float* X  = (z == 0) ? xq : (z == 1) ? xk : xv;
    const float* W  = (z == 0) ? wq : (z == 1) ? wk : wv;
    const float* Bi = (z == 0) ? bq : (z == 1) ? bk : bv;
    float*       O  = (z == 0) ? g_qh : (z == 1) ? g_kh : g_vh;

    int tid = threadIdx.x;
    int lane = tid & 31, wid = tid >> 5;
    int g = lane >> 2, ct = lane & 3;
    int mb = (wid >> 1) * 64, nb = (wid & 1) * 64;
    int m0 = blockIdx.y * 256, n0 = blockIdx.x * 128;

    float c[4][8][4];
    #pragma unroll
    for (int i = 0; i < 4; i++)
        #pragma unroll
        for (int j = 0; j < 8; j++)
            #pragma unroll
            for (int t = 0; t < 4; t++) c[i][j][t] = 0.0f;

    float4 pa[4], pb[2];
    #pragma unroll
    for (int it = 0; it < 4; it++) {
        int fi = tid + it * 256; int r = fi >> 2, c4 = (fi & 3) << 2;
        pa[it] = *(const float4*)(X + (size_t)(m0 + r) * DM + c4);
    }
    #pragma unroll
    for (int it = 0; it < 2; it++) {
        int fi = tid + it * 256; int r = fi >> 2, c4 = (fi & 3) << 2;
        pb[it] = *(const float4*)(W + (size_t)(n0 + r) * DM + c4);
    }

    for (int k0 = 0; k0 < DM; k0 += 16) {
        #pragma unroll
        for (int it = 0; it < 4; it++) {
            int fi = tid + it * 256; int r = fi >> 2, c4 = (fi & 3) << 2;
            *(uint4*)&As[r * 20 + c4] =
                make_uint4(tf32c(pa[it].x), tf32c(pa[it].y), tf32c(pa[it].z), tf32c(pa[it].w));
        }
        #pragma unroll
        for (int it = 0; it < 2; it++) {
            int fi = tid + it * 256; int r = fi >> 2, c4 = (fi & 3) << 2;
            *(uint4*)&Bs[r * 20 + c4] =
                make_uint4(tf32c(pb[it].x), tf32c(pb[it].y), tf32c(pb[it].z), tf32c(pb[it].w));
        }
        __syncthreads();
        if (k0 + 16 < DM) {
            #pragma unroll
            for (int it = 0; it < 4; it++) {
                int fi = tid + it * 256; int r = fi >> 2, c4 = (fi & 3) << 2;
                pa[it] = *(const float4*)(X + (size_t)(m0 + r) * DM + k0 + 16 + c4);
            }
            #pragma unroll
            for (int it = 0; it < 2; it++) {
                int fi = tid + it * 256; int r = fi >> 2, c4 = (fi & 3) << 2;
                pb[it] = *(const float4*)(W + (size_t)(n0 + r) * DM + k0 + 16 + c4);
            }
        }
        #pragma unroll
        for (int ks = 0; ks < 16; ks += 8) {
            uint32_t af[4][4], bf[8][2];
            #pragma unroll
            for (int i = 0; i < 4; i++) {
                int r0 = (mb + i * 16 + g) * 20 + ks + ct;
                af[i][0] = As[r0];       af[i][2] = As[r0 + 4];
                af[i][1] = As[r0 + 160]; af[i][3] = As[r0 + 164];
            }
            #pragma unroll
            for (int j = 0; j < 8; j++) {
                int b0 = (nb + j * 8 + g) * 20 + ks + ct;
                bf[j][0] = Bs[b0]; bf[j][1] = Bs[b0 + 4];
            }
            #pragma unroll
            for (int i = 0; i < 4; i++)
                #pragma unroll
                for (int j = 0; j < 8; j++) mma8(c[i][j], af[i], bf[j]);
        }
        __syncthreads();
    }
    // epilogue: bias + scatter to [B,H,S,Dh]
    #pragma unroll
    for (int i = 0; i < 4; i++) {
        int row = m0 + mb + i * 16 + g;
        int b_ = row >> 11, s_ = row & (SS - 1);
        #pragma unroll
        for (int j = 0; j < 8; j++) {
            int col = n0 + nb + j * 8 + ct * 2;
            int h = col >> 6, dh = col & 63;
            float2 bi = *(const float2*)&Bi[col];
            size_t base = ((size_t)(b_ * HH + h) * SS + s_) * DH + dh;
            *(float2*)&O[base]          = make_float2(c[i][j][0] + bi.x, c[i][j][1] + bi.y);
            *(float2*)&O[base + 8 * DH] = make_float2(c[i][j][2] + bi.x, c[i][j][3] + bi.y);
        }
    }
}

// ---------------------------------------------------------------------------
// K2: fused attention. Per CTA: (bh, 128 q-rows), n processed in 256-supertiles.
// QK warp tile 64q x 64n (two interleaved 32-wide n-strips, one per half).
// Pass A: rowsum(exp). Pass B: recompute, write score once, PV per 128-half.
// ---------------------------------------------------------------------------
#define AT_QS  0                        // 128*68  = 8704
#define AT_KS  8704                     // 256*68  = 17408
#define AT_VS  26112                    // 128*72  = 9216
#define AT_PS  35328                    // 128*132 = 16896
#define AT_RP  52224                    // 512
#define AT_INV 52736                    // 128
#define AT_WORDS 52864
#define AT_BYTES (AT_WORDS * 4)

__global__ __launch_bounds__(256, 1) void k_attn(
    const float* __restrict__ mask, float* __restrict__ score)
{
    extern __shared__ uint32_t sm[];
    uint32_t* Qs = sm + AT_QS;
    uint32_t* Ks = sm + AT_KS;
    uint32_t* Vs = sm + AT_VS;
    uint32_t* Ps = sm + AT_PS;
    float* rowp  = (float*)(sm + AT_RP);
    float* invs  = (float*)(sm + AT_INV);

    int bh = blockIdx.y, q0 = blockIdx.x * 128;
    const float* Q = g_qh + (size_t)bh * SS * DH;
    const float* K = g_kh + (size_t)bh * SS * DH;
    const float* V = g_vh + (size_t)bh * SS * DH;

    int tid = threadIdx.x, lane = tid & 31, wid = tid >> 5;
    int g = lane >> 2, ct = lane & 3;
    int mb = (wid & 1) * 64;        // QK q-block (64)
    int sn = wid >> 1;              // n-strip 0..3 (32-wide, per half)
    int pm = (wid & 1) * 32;        // PV dh strip
    int pn = sn * 32;               // PV q strip

    // Q tile resident
    #pragma unroll
    for (int it = 0; it < 8; it++) {
        int fi = tid + it * 256;
        int r = fi >> 4, c4 = (fi & 15) << 2;
        float4 a = *(const float4*)(Q + (size_t)(q0 + r) * DH + c4);
        *(uint4*)&Qs[r * 68 + c4] = make_uint4(tf32c(a.x), tf32c(a.y), tf32c(a.z), tf32c(a.w));
    }

    float c[4][8][4];
    float rs[4][2];
    #pragma unroll
    for (int i = 0; i < 4; i++) { rs[i][0] = 0.0f; rs[i][1] = 0.0f; }

    // ---------------- Pass A: row sums ----------------
    for (int n0 = 0; n0 < SS; n0 += 256) {
        __syncthreads();
        #pragma unroll
        for (int it = 0; it < 16; it++) {
            int fi = tid + it * 256;
            int r = fi >> 4, c4 = (fi & 15) << 2;
            float4 a = *(const float4*)(K + (size_t)(n0 + r) * DH + c4);
            *(uint4*)&Ks[r * 68 + c4] = make_uint4(tf32c(a.x), tf32c(a.y), tf32c(a.z), tf32c(a.w));
        }
        __syncthreads();
        #pragma unroll
        for (int i = 0; i < 4; i++)
            #pragma unroll
            for (int j = 0; j < 8; j++)
                #pragma unroll
                for (int t = 0; t < 4; t++) c[i][j][t] = 0.0f;
        #pragma unroll
        for (int ks = 0; ks < DH; ks += 8) {
            uint32_t af[4][4], bf[8][2];
            #pragma unroll
            for (int i = 0; i < 4; i++) {
                int r0 = (mb + i * 16 + g) * 68 + ks + ct;
                af[i][0] = Qs[r0];       af[i][2] = Qs[r0 + 4];
                af[i][1] = Qs[r0 + 544]; af[i][3] = Qs[r0 + 548];
            }
            #pragma unroll
            for (int j = 0; j < 8; j++) {
                int ncol = (j < 4) ? (sn * 32 + j * 8) : (128 + sn * 32 + (j - 4) * 8);
                int b0 = (ncol + g) * 68 + ks + ct;
                bf[j][0] = Ks[b0]; bf[j][1] = Ks[b0 + 4];
            }
            #pragma unroll
            for (int i = 0; i < 4; i++)
                #pragma unroll
                for (int j = 0; j < 8; j++) mma8(c[i][j], af[i], bf[j]);
        }
        #pragma unroll
        for (int i = 0; i < 4; i++) {
            int row = q0 + mb + i * 16 + g;
            #pragma unroll
            for (int j = 0; j < 8; j++) {
                int ncol = (j < 4) ? (sn * 32 + j * 8) : (128 + sn * 32 + (j - 4) * 8);
                int colg = n0 + ncol + ct * 2;
                float2 mk0 = *(const float2*)&mask[(size_t)row * SS + colg];
                rs[i][0] += fexp(fmaf(c[i][j][0], 0.125f, mk0.x))
                          + fexp(fmaf(c[i][j][1], 0.125f, mk0.y));
                float2 mk1 = *(const float2*)&mask[(size_t)(row + 8) * SS + colg];
                rs[i][1] += fexp(fmaf(c[i][j][2], 0.125f, mk1.x))
                          + fexp(fmaf(c[i][j][3], 0.125f, mk1.y));
            }
        }
    }
    #pragma unroll
    for (int i = 0; i < 4; i++) {
        #pragma unroll
        for (int hh = 0; hh < 2; hh++) {
            float v = rs[i][hh];
            v += __shfl_xor_sync(0xffffffff, v, 1);
            v += __shfl_xor_sync(0xffffffff, v, 2);
            if (ct == 0) rowp[(mb + i * 16 + hh * 8 + g) * 4 + sn] = v;
        }
    }
    __syncthreads();
    if (tid < 128)
        invs[tid] = 1.0f / (rowp[tid*4] + rowp[tid*4+1] + rowp[tid*4+2] + rowp[tid*4+3]);

    // ---------------- Pass B: score + ctx ----------------
    float d[2][4][4];
    #pragma unroll
    for (int i = 0; i < 2; i++)
        #pragma unroll
        for (int j = 0; j < 4; j++)
            #pragma unroll
            for (int t = 0; t < 4; t++) d[i][j][t] = 0.0f;

    size_t sbase = (size_t)bh * SS * SS;

    for (int n0 = 0; n0 < SS; n0 += 256) {
        __syncthreads();
        // K supertile + V half0
        #pragma unroll
        for (int it = 0; it < 16; it++) {
            int fi = tid + it * 256;
            int r = fi >> 4, c4 = (fi & 15) << 2;
            float4 a = *(const float4*)(K + (size_t)(n0 + r) * DH + c4);
            *(uint4*)&Ks[r * 68 + c4] = make_uint4(tf32c(a.x), tf32c(a.y), tf32c(a.z), tf32c(a.w));
        }
        #pragma unroll
        for (int it = 0; it < 8; it++) {
            int fi = tid + it * 256;
            int r = fi >> 4, c4 = (fi & 15) << 2;
            float4 vv = *(const float4*)(V + (size_t)(n0 + r) * DH + c4);
            *(uint4*)&Vs[r * 72 + c4] = make_uint4(tf32c(vv.x), tf32c(vv.y), tf32c(vv.z), tf32c(vv.w));
        }
        __syncthreads();
        #pragma unroll
        for (int i = 0; i < 4; i++)
            #pragma unroll
            for (int j = 0; j < 8; j++)
                #pragma unroll
                for (int t = 0; t < 4; t++) c[i][j][t] = 0.0f;
        #pragma unroll
        for (int ks = 0; ks < DH; ks += 8) {
            uint32_t af[4][4], bf[8][2];
            #pragma unroll
            for (int i = 0; i < 4; i++) {
                int r0 = (mb + i * 16 + g) * 68 + ks + ct;
                af[i][0] = Qs[r0];       af[i][2] = Qs[r0 + 4];
                af[i][1] = Qs[r0 + 544]; af[i][3] = Qs[r0 + 548];
            }
            #pragma unroll
            for (int j = 0; j < 8; j++) {
                int ncol = (j < 4) ? (sn * 32 + j * 8) : (128 + sn * 32 + (j - 4) * 8);
                int b0 = (ncol + g) * 68 + ks + ct;
                bf[j][0] = Ks[b0]; bf[j][1] = Ks[b0 + 4];
            }
            #pragma unroll
            for (int i = 0; i < 4; i++)
                #pragma unroll
                for (int j = 0; j < 8; j++) mma8(c[i][j], af[i], bf[j]);
        }

        #pragma unroll
        for (int half = 0; half < 2; half++) {
            if (half == 1) {
                __syncthreads();   // PV h0 readers of Vs done
                #pragma unroll
                for (int it = 0; it < 8; it++) {
                    int fi = tid + it * 256;
                    int r = fi >> 4, c4 = (fi & 15) << 2;
                    float4 vv = *(const float4*)(V + (size_t)(n0 + 128 + r) * DH + c4);
                    *(uint4*)&Vs[r * 72 + c4] =
                        make_uint4(tf32c(vv.x), tf32c(vv.y), tf32c(vv.z), tf32c(vv.w));
                }
            }
            // epilogue for this half: p -> score gmem + Ps smem
            #pragma unroll
            for (int i = 0; i < 4; i++) {
                int rloc = mb + i * 16 + g;
                float iv0 = invs[rloc], iv1 = invs[rloc + 8];
                int grow = q0 + rloc;
                #pragma unroll
                for (int jj = 0; jj < 4; jj++) {
                    int j = half * 4 + jj;
                    int kcol = sn * 32 + jj * 8 + ct * 2;       // 0..127 within half
                    int colg = n0 + half * 128 + kcol;
                    float2 mk0 = *(const float2*)&mask[(size_t)grow * SS + colg];
                    float p0 = fexp(fmaf(c[i][j][0], 0.125f, mk0.x)) * iv0;
                    float p1 = fexp(fmaf(c[i][j][1], 0.125f, mk0.y)) * iv0;
                    *(float2*)&score[sbase + (size_t)grow * SS + colg] = make_float2(p0, p1);
                    Ps[rloc * 132 + kcol]     = tf32c(p0);
                    Ps[rloc * 132 + kcol + 1] = tf32c(p1);
                    float2 mk1 = *(const float2*)&mask[(size_t)(grow + 8) * SS + colg];
                    float p2 = fexp(fmaf(c[i][j][2], 0.125f, mk1.x)) * iv1;
                    float p3 = fexp(fmaf(c[i][j][3], 0.125f, mk1.y)) * iv1;
                    *(float2*)&score[sbase + (size_t)(grow + 8) * SS + colg] = make_float2(p2, p3);
                    Ps[(rloc + 8) * 132 + kcol]     = tf32c(p2);
                    Ps[(rloc + 8) * 132 + kcol + 1] = tf32c(p3);
                }
            }
            __syncthreads();   // Ps + Vs ready
            // PV: D += V^T x P^T over k=128 (this half)
            #pragma unroll
            for (int ks = 0; ks < 128; ks += 8) {
                uint32_t af[2][4], bf[4][2];
                #pragma unroll
                for (int i = 0; i < 2; i++) {
                    int a0 = (ks + ct) * 72 + pm + i * 16 + g;
                    af[i][0] = Vs[a0];       af[i][1] = Vs[a0 + 8];
                    af[i][2] = Vs[a0 + 288]; af[i][3] = Vs[a0 + 296];
                }
                #pragma unroll
                for (int j = 0; j < 4; j++) {
                    int b0 = (pn + j * 8 + g) * 132 + ks + ct;
                    bf[j][0] = Ps[b0]; bf[j][1] = Ps[b0 + 4];
                }
                #pragma unroll
                for (int i = 0; i < 2; i++)
                    #pragma unroll
                    for (int j = 0; j < 4; j++) mma8(d[i][j], af[i], bf[j]);
            }
            if (half == 0) __syncthreads();   // allow Vs h1 overwrite + Ps reuse
        }
    }
    __syncthreads();
    // stage ctx^T -> smem (reuse Ps as float [q=128][dh stride 68]) for coalesced STG
    float* ctxs = (float*)Ps;
    #pragma unroll
    for (int i = 0; i < 2; i++) {
        int dh = pm + i * 16 + g;
        #pragma unroll
        for (int j = 0; j < 4; j++) {
            int qq = pn + j * 8 + ct * 2;
            ctxs[qq * 68 + dh]           = d[i][j][0];
            ctxs[(qq + 1) * 68 + dh]     = d[i][j][1];
            ctxs[qq * 68 + dh + 8]       = d[i][j][2];
            ctxs[(qq + 1) * 68 + dh + 8] = d[i][j][3];
        }
    }
    __syncthreads();
    float* C = g_ctx + (size_t)bh * SS * DH + (size_t)q0 * DH;
    #pragma unroll
    for (int it = 0; it < 8; it++) {
        int fi = tid + it * 256;
        int r = fi >> 4, c4 = (fi & 15) << 2;
        *(float4*)(C + (size_t)r * DH + c4) = *(float4*)&ctxs[r * 68 + c4];
    }
}

// ---------------------------------------------------------------------------
// K4: output projection. 256x128 tile, warp 64x64, reg-prefetch double buffer.
// ---------------------------------------------------------------------------
__global__ __launch_bounds__(256) void k_oproj(
    const float* __restrict__ wo, const float* __restrict__ bo, float* __restrict__ out)
{
    __shared__ uint32_t As[256*20];
    __shared__ uint32_t Bs[128*20];
    int tid = threadIdx.x;
    int lane = tid & 31, wid = tid >> 5;
    int g = lane >> 2, ct = lane & 3;
    int mb = (wid >> 1) * 64, nb = (wid & 1) * 64;
    int m0 = blockIdx.y * 256, n0 = blockIdx.x * 128;

    float c[4][8][4];
    #pragma unroll
    for (int i = 0; i < 4; i++)
        #pragma unroll
        for (int j = 0; j < 8; j++)
            #pragma unroll
            for (int t = 0; t < 4; t++) c[i][j][t] = 0.0f;

    float4 pa[4], pb[2];
    #pragma unroll
    for (int it = 0; it < 4; it++) {
        int fi = tid + it * 256; int r = fi >> 2, c4 = (fi & 3) << 2;
        int m = m0 + r;
        int b_ = m >> 11, s_ = m & (SS - 1);
        int h = c4 >> 6, dh = c4 & 63;
        pa[it] = *(const float4*)(g_ctx + ((size_t)(b_ * HH + h) * SS + s_) * DH + dh);
    }
    #pragma unroll
    for (int it = 0; it < 2; it++) {
        int fi = tid + it * 256; int r = fi >> 2, c4 = (fi & 3) << 2;
        pb[it] = *(const float4*)(wo + (size_t)(n0 + r) * DM + c4);
    }

    for (int k0 = 0; k0 < DM; k0 += 16) {
        #pragma unroll
        for (int it = 0; it < 4; it++) {
            int fi = tid + it * 256; int r = fi >> 2, c4 = (fi & 3) << 2;
            *(uint4*)&As[r * 20 + c4] =
                make_uint4(tf32c(pa[it].x), tf32c(pa[it].y), tf32c(pa[it].z), tf32c(pa[it].w));
        }
        #pragma unroll
        for (int it = 0; it < 2; it++) {
            int fi = tid + it * 256; int r = fi >> 2, c4 = (fi & 3) << 2;
            *(uint4*)&Bs[r * 20 + c4] =
                make_uint4(tf32c(pb[it].x), tf32c(pb[it].y), tf32c(pb[it].z), tf32c(pb[it].w));
        }
        __syncthreads();
        if (k0 + 16 < DM) {
            #pragma unroll
            for (int it = 0; it < 4; it++) {
                int fi = tid + it * 256; int r = fi >> 2, c4 = (fi & 3) << 2;
                int m = m0 + r;
                int b_ = m >> 11, s_ = m & (SS - 1);
                int kidx = k0 + 16 + c4;
                int h = kidx >> 6, dh = kidx & 63;
                pa[it] = *(const float4*)(g_ctx + ((size_t)(b_ * HH + h) * SS + s_) * DH + dh);
            }
            #pragma unroll
            for (int it = 0; it < 2; it++) {
                int fi = tid + it * 256; int r = fi >> 2, c4 = (fi & 3) << 2;
                pb[it] = *(const float4*)(wo + (size_t)(n0 + r) * DM + k0 + 16 + c4);
            }
        }
        #pragma unroll
        for (int ks = 0; ks < 16; ks += 8) {
            uint32_t af[4][4], bf[8][2];
            #pragma unroll
            for (int i = 0; i < 4; i++) {
                int r0 = (mb + i * 16 + g) * 20 + ks + ct;
                af[i][0] = As[r0];       af[i][2] = As[r0 + 4];
                af[i][1] = As[r0 + 160]; af[i][3] = As[r0 + 164];
            }
            #pragma unroll
            for (int j = 0; j < 8; j++) {
                int b0 = (nb + j * 8 + g) * 20 + ks + ct;
                bf[j][0] = Bs[b0]; bf[j][1] = Bs[b0 + 4];
            }
            #pragma unroll
            for (int i = 0; i < 4; i++)
                #pragma unroll
                for (int j = 0; j < 8; j++) mma8(c[i][j], af[i], bf[j]);
        }
        __syncthreads();
    }
    #pragma unroll
    for (int i = 0; i < 4; i++) {
        int row = m0 + mb + i * 16 + g;
        #pragma unroll
        for (int j = 0; j < 8; j++) {
            int col = n0 + nb + j * 8 + ct * 2;
            float2 bi = *(const float2*)&bo[col];
            *(float2*)&out[(size_t)row * DM + col] =
                make_float2(c[i][j][0] + bi.x, c[i][j][1] + bi.y);
            *(float2*)&out[(size_t)(row + 8) * DM + col] =
                make_float2(c[i][j][2] + bi.x, c[i][j][3] + bi.y);
        }
    }
}

// ---------------------------------------------------------------------------
extern "C" void kernel_launch(void* const* d_in, const int* in_sizes, int n_in,
                              void* d_out, int out_size)
{
    const float* q    = (const float*)d_in[0];
    const float* k    = (const float*)d_in[1];
    const float* v    = (const float*)d_in[2];
    const float* mask = (const float*)d_in[3];
    const float* w_q  = (const float*)d_in[4];
    const float* b_q  = (const float*)d_in[5];
    const float* w_k  = (const float*)d_in[6];
    const float* b_k  = (const float*)d_in[7];
    const float* w_v  = (const float*)d_in[8];
    const float* b_v  = (const float*)d_in[9];
    const float* w_o  = (const float*)d_in[10];
    const float* b_o  = (const float*)d_in[11];

    float* out   = (float*)d_out;                        // x: [B,S,DM]
    float* score = out + (size_t)BB * SS * DM;           // score: [B,H,S,S]

    cudaFuncSetAttribute(k_attn, cudaFuncAttributeMaxDynamicSharedMemorySize, AT_BYTES);

    k_qkv_proj<<<dim3(DM/128, (BB*SS)/256, 3), 256>>>(q, k, v, w_q, w_k, w_v, b_q, b_k, b_v);
    k_attn<<<dim3(SS/128, BHT), 256, AT_BYTES>>>(mask, score);
    k_oproj<<<dim3(DM/128, (BB*SS)/256), 256>>>(w_o, b_o, out);
}

// round 6
// speedup vs baseline: 1.1275x; 1.1275x over previous
#include <cuda_runtime.h>
#include <cuda_bf16.h>
#include <cstdint>

// Problem constants
#define BB   4
#define SS   2048
#define HH   16
#define DH   64
#define DM   1024
#define BHT  (BB*HH)          // 64

// Scratch (device globals: allocation-free)
__device__ float g_qh [(size_t)BB*HH*SS*DH];   // [B,H,S,Dh]
__device__ float g_kh [(size_t)BB*HH*SS*DH];
__device__ float g_vh [(size_t)BB*HH*SS*DH];
__device__ float g_ctx[(size_t)BB*HH*SS*DH];

// fp32 -> tf32 round-to-nearest
__device__ __forceinline__ uint32_t tf32c(float x) {
    uint32_t u;
    asm("cvt.rna.tf32.f32 %0, %1;" : "=r"(u) : "f"(x));
    return u;
}

// m16n8k8 tf32 MMA, fp32 accumulate
__device__ __forceinline__ void mma8(float c[4], const uint32_t a[4], const uint32_t b[2]) {
    asm volatile(
        "mma.sync.aligned.m16n8k8.row.col.f32.tf32.tf32.f32 "
        "{%0,%1,%2,%3},{%4,%5,%6,%7},{%8,%9},{%0,%1,%2,%3};"
        : "+f"(c[0]), "+f"(c[1]), "+f"(c[2]), "+f"(c[3])
        : "r"(a[0]), "r"(a[1]), "r"(a[2]), "r"(a[3]), "r"(b[0]), "r"(b[1]));
}

// FMA-only exp
__device__ __forceinline__ float fexp(float x) {
    float y = x * 1.4426950408889634f;
    float r = rintf(y);
    float c = (y - r) * 0.6931471805599453f;
    float p = 1.3888889e-3f;
    p = fmaf(p, c, 8.3333333e-3f);
    p = fmaf(p, c, 4.1666667e-2f);
    p = fmaf(p, c, 1.6666667e-1f);
    p = fmaf(p, c, 0.5f);
    p = fmaf(p, c, 1.0f);
    p = fmaf(p, c, 1.0f);
    return p * __int_as_float(((int)r + 127) << 23);
}

// cp.async helpers
__device__ __forceinline__ void cpa16(uint32_t saddr, const void* g) {
    asm volatile("cp.async.ca.shared.global [%0], [%1], 16;" :: "r"(saddr), "l"(g));
}
#define CP_COMMIT asm volatile("cp.async.commit_group;")
#define CP_WAIT0  asm volatile("cp.async.wait_group 0;")
#define CP_WAIT1  asm volatile("cp.async.wait_group 1;")

// ---------------------------------------------------------------------------
// K1: fused QKV projection. 128x128 tile, 64x32 warp tiles, BK=16.
// cp.async double-buffered smem (fp32); cvt.rna at fragment load.
// ---------------------------------------------------------------------------
__global__ __launch_bounds__(256, 2) void k_qkv_proj(
    const float* __restrict__ xq, const float* __restrict__ xk, const float* __restrict__ xv,
    const float* __restrict__ wq, const float* __restrict__ wk, const float* __restrict__ wv,
    const float* __restrict__ bq, const float* __restrict__ bk, const float* __restrict__ bv)
{
    __shared__ float As[2][2560];   // [stage][r*20 + k]
    __shared__ float Bs[2][2560];
    int z = blockIdx.z;
    const float* X  = (z == 0) ? xq : (z == 1) ? xk : xv;
    const float* W  = (z == 0) ? wq : (z == 1) ? wk : wv;
    const float* Bi = (z == 0) ? bq : (z == 1) ? bk : bv;
    float*       O  = (z == 0) ? g_qh : (z == 1) ? g_kh : g_vh;

    int tid = threadIdx.x;
    int lane = tid & 31, wid = tid >> 5;
    int g = lane >> 2, ct = lane & 3;
    int mb = (wid >> 2) * 64, nb = (wid & 3) * 32;
    int m0 = blockIdx.y * 128, n0 = blockIdx.x * 128;

    uint32_t asb = (uint32_t)__cvta_generic_to_shared(&As[0][0]);
    uint32_t bsb = (uint32_t)__cvta_generic_to_shared(&Bs[0][0]);
    int rl = tid >> 2, cl = (tid & 3) << 2;   // this thread copies rows rl, rl+64

    float c[4][4][4];
    #pragma unroll
    for (int i = 0; i < 4; i++)
        #pragma unroll
        for (int j = 0; j < 4; j++)
            #pragma unroll
            for (int t = 0; t < 4; t++) c[i][j][t] = 0.0f;

    // prologue: stage 0
    cpa16(asb + (0 * 2560 + rl * 20 + cl) * 4,        X + (size_t)(m0 + rl) * DM + cl);
    cpa16(asb + (0 * 2560 + (rl + 64) * 20 + cl) * 4, X + (size_t)(m0 + rl + 64) * DM + cl);
    cpa16(bsb + (0 * 2560 + rl * 20 + cl) * 4,        W + (size_t)(n0 + rl) * DM + cl);
    cpa16(bsb + (0 * 2560 + (rl + 64) * 20 + cl) * 4, W + (size_t)(n0 + rl + 64) * DM + cl);
    CP_COMMIT;

    for (int k0 = 0, st = 0; k0 < DM; k0 += 16, st ^= 1) {
        CP_WAIT0;
        __syncthreads();
        if (k0 + 16 < DM) {
            int kn = k0 + 16, so = (st ^ 1) * 2560;
            cpa16(asb + (so + rl * 20 + cl) * 4,        X + (size_t)(m0 + rl) * DM + kn + cl);
            cpa16(asb + (so + (rl + 64) * 20 + cl) * 4, X + (size_t)(m0 + rl + 64) * DM + kn + cl);
            cpa16(bsb + (so + rl * 20 + cl) * 4,        W + (size_t)(n0 + rl) * DM + kn + cl);
            cpa16(bsb + (so + (rl + 64) * 20 + cl) * 4, W + (size_t)(n0 + rl + 64) * DM + kn + cl);
        }
        CP_COMMIT;
        const float* Af = &As[st][0];
        const float* Bf = &Bs[st][0];
        #pragma unroll
        for (int ks = 0; ks < 16; ks += 8) {
            uint32_t af[4][4], bf[4][2];
            #pragma unroll
            for (int i = 0; i < 4; i++) {
                int r0 = (mb + i * 16 + g) * 20 + ks + ct;
                af[i][0] = tf32c(Af[r0]);       af[i][2] = tf32c(Af[r0 + 4]);
                af[i][1] = tf32c(Af[r0 + 160]); af[i][3] = tf32c(Af[r0 + 164]);
            }
            #pragma unroll
            for (int j = 0; j < 4; j++) {
                int b0 = (nb + j * 8 + g) * 20 + ks + ct;
                bf[j][0] = tf32c(Bf[b0]); bf[j][1] = tf32c(Bf[b0 + 4]);
            }
            #pragma unroll
            for (int i = 0; i < 4; i++)
                #pragma unroll
                for (int j = 0; j < 4; j++) mma8(c[i][j], af[i], bf[j]);
        }
    }
    __syncthreads();
    // epilogue: bias + scatter to [B,H,S,Dh]
    #pragma unroll
    for (int i = 0; i < 4; i++) {
        int row = m0 + mb + i * 16 + g;
        int b_ = row >> 11, s_ = row & (SS - 1);
        #pragma unroll
        for (int j = 0; j < 4; j++) {
            int col = n0 + nb + j * 8 + ct * 2;
            int h = col >> 6, dh = col & 63;
            float2 bi = *(const float2*)&Bi[col];
            size_t base = ((size_t)(b_ * HH + h) * SS + s_) * DH + dh;
            *(float2*)&O[base]          = make_float2(c[i][j][0] + bi.x, c[i][j][1] + bi.y);
            *(float2*)&O[base + 8 * DH] = make_float2(c[i][j][2] + bi.x, c[i][j][3] + bi.y);
        }
    }
}

// ---------------------------------------------------------------------------
// K2: fused attention, round-3 geometry + cp.async pipelining.
// smem words: Qs(tf32)8704 @0 | Ks(fp32,2st)17408 @8704 | Vs(fp32)9216 @26112
//             Ps(tf32)16896 @35328 | rowp 512 @52224 | invs 128 @52736
// ---------------------------------------------------------------------------
#define AT_QS  0
#define AT_KS  8704
#define AT_VS  26112
#define AT_PS  35328
#define AT_RP  52224
#define AT_INV 52736
#define AT_WORDS 52864
#define AT_BYTES (AT_WORDS * 4)

__global__ __launch_bounds__(256, 1) void k_attn(
    const float* __restrict__ mask, float* __restrict__ score)
{
    extern __shared__ uint32_t sm[];
    uint32_t* Qs = sm + AT_QS;
    float* Ksf   = (float*)(sm + AT_KS);
    float* Vsf   = (float*)(sm + AT_VS);
    uint32_t* Ps = sm + AT_PS;
    float* rowp  = (float*)(sm + AT_RP);
    float* invs  = (float*)(sm + AT_INV);
    uint32_t smb = (uint32_t)__cvta_generic_to_shared(sm);

    int bh = blockIdx.y, q0 = blockIdx.x * 128;
    const float* Q = g_qh + (size_t)bh * SS * DH;
    const float* K = g_kh + (size_t)bh * SS * DH;
    const float* V = g_vh + (size_t)bh * SS * DH;

    int tid = threadIdx.x, lane = tid & 31, wid = tid >> 5;
    int g = lane >> 2, ct = lane & 3;
    int mb = (wid >> 2) * 64, nb = (wid & 3) * 32;   // QK warp tile 64x32
    int pm = (wid & 1) * 32, pn = (wid >> 1) * 32;   // PV warp tile

    // Q tile -> tf32 smem (one-time)
    #pragma unroll
    for (int it = 0; it < 8; it++) {
        int fi = tid + it * 256;
        int r = fi >> 4, c4 = (fi & 15) << 2;
        float4 a = *(const float4*)(Q + (size_t)(q0 + r) * DH + c4);
        *(uint4*)&Qs[r * 68 + c4] = make_uint4(tf32c(a.x), tf32c(a.y), tf32c(a.z), tf32c(a.w));
    }

    float c[4][4][4];
    float rs[4][2];
    #pragma unroll
    for (int i = 0; i < 4; i++) { rs[i][0] = 0.0f; rs[i][1] = 0.0f; }

    // ---------------- Pass A: row sums ----------------
    // prologue: K tile 0 -> stage 0
    #pragma unroll
    for (int it = 0; it < 8; it++) {
        int fi = tid + it * 256;
        int r = fi >> 4, c4 = (fi & 15) << 2;
        cpa16(smb + (AT_KS + r * 68 + c4) * 4, K + (size_t)r * DH + c4);
    }
    CP_COMMIT;

    for (int n0 = 0, st = 0; n0 < SS; n0 += 128, st ^= 1) {
        CP_WAIT0;
        __syncthreads();
        if (n0 + 128 < SS) {
            int so = AT_KS + (st ^ 1) * 8704;
            #pragma unroll
            for (int it = 0; it < 8; it++) {
                int fi = tid + it * 256;
                int r = fi >> 4, c4 = (fi & 15) << 2;
                cpa16(smb + (so + r * 68 + c4) * 4, K + (size_t)(n0 + 128 + r) * DH + c4);
            }
        }
        CP_COMMIT;
        const float* Kf = Ksf + st * 8704;
        #pragma unroll
        for (int i = 0; i < 4; i++)
            #pragma unroll
            for (int j = 0; j < 4; j++)
                #pragma unroll
                for (int t = 0; t < 4; t++) c[i][j][t] = 0.0f;
        #pragma unroll
        for (int ks = 0; ks < DH; ks += 8) {
            uint32_t af[4][4], bf[4][2];
            #pragma unroll
            for (int i = 0; i < 4; i++) {
                int r0 = (mb + i * 16 + g) * 68 + ks + ct;
                af[i][0] = Qs[r0];       af[i][2] = Qs[r0 + 4];
                af[i][1] = Qs[r0 + 544]; af[i][3] = Qs[r0 + 548];
            }
            #pragma unroll
            for (int j = 0; j < 4; j++) {
                int b0 = (nb + j * 8 + g) * 68 + ks + ct;
                bf[j][0] = tf32c(Kf[b0]); bf[j][1] = tf32c(Kf[b0 + 4]);
            }
            #pragma unroll
            for (int i = 0; i < 4; i++)
                #pragma unroll
                for (int j = 0; j < 4; j++) mma8(c[i][j], af[i], bf[j]);
        }
        #pragma unroll
        for (int i = 0; i < 4; i++) {
            int row = q0 + mb + i * 16 + g;
            #pragma unroll
            for (int j = 0; j < 4; j++) {
                int colg = n0 + nb + j * 8 + ct * 2;
                float2 mk0 = *(const float2*)&mask[(size_t)row * SS + colg];
                rs[i][0] += fexp(fmaf(c[i][j][0], 0.125f, mk0.x))
                          + fexp(fmaf(c[i][j][1], 0.125f, mk0.y));
                float2 mk1 = *(const float2*)&mask[(size_t)(row + 8) * SS + colg];
                rs[i][1] += fexp(fmaf(c[i][j][2], 0.125f, mk1.x))
                          + fexp(fmaf(c[i][j][3], 0.125f, mk1.y));
            }
        }
    }
    #pragma unroll
    for (int i = 0; i < 4; i++) {
        #pragma unroll
        for (int hh = 0; hh < 2; hh++) {
            float v = rs[i][hh];
            v += __shfl_xor_sync(0xffffffff, v, 1);
            v += __shfl_xor_sync(0xffffffff, v, 2);
            if (ct == 0) rowp[(mb + i * 16 + hh * 8 + g) * 4 + (wid & 3)] = v;
        }
    }
    __syncthreads();
    if (tid < 128)
        invs[tid] = 1.0f / (rowp[tid*4] + rowp[tid*4+1] + rowp[tid*4+2] + rowp[tid*4+3]);

    // ---------------- Pass B: score + ctx ----------------
    float d[2][4][4];
    #pragma unroll
    for (int i = 0; i < 2; i++)
        #pragma unroll
        for (int j = 0; j < 4; j++)
            #pragma unroll
            for (int t = 0; t < 4; t++) d[i][j][t] = 0.0f;

    size_t sbase = (size_t)bh * SS * SS;

    // prologue: K tile 0 -> stage 0
    #pragma unroll
    for (int it = 0; it < 8; it++) {
        int fi = tid + it * 256;
        int r = fi >> 4, c4 = (fi & 15) << 2;
        cpa16(smb + (AT_KS + r * 68 + c4) * 4, K + (size_t)r * DH + c4);
    }
    CP_COMMIT;

    for (int n0 = 0, st = 0; n0 < SS; n0 += 128, st ^= 1) {
        CP_WAIT0;            // K_cur ready
        __syncthreads();     // prev PV readers of Vs/Ps done; invs visible (iter 0)
        // V_cur (own group)
        #pragma unroll
        for (int it = 0; it < 8; it++) {
            int fi = tid + it * 256;
            int r = fi >> 4, c4 = (fi & 15) << 2;
            cpa16(smb + (AT_VS + r * 72 + c4) * 4, V + (size_t)(n0 + r) * DH + c4);
        }
        CP_COMMIT;
        // K_next (own group, possibly empty)
        if (n0 + 128 < SS) {
            int so = AT_KS + (st ^ 1) * 8704;
            #pragma unroll
            for (int it = 0; it < 8; it++) {
                int fi = tid + it * 256;
                int r = fi >> 4, c4 = (fi & 15) << 2;
                cpa16(smb + (so + r * 68 + c4) * 4, K + (size_t)(n0 + 128 + r) * DH + c4);
            }
        }
        CP_COMMIT;

        const float* Kf = Ksf + st * 8704;
        #pragma unroll
        for (int i = 0; i < 4; i++)
            #pragma unroll
            for (int j = 0; j < 4; j++)
                #pragma unroll
                for (int t = 0; t < 4; t++) c[i][j][t] = 0.0f;
        #pragma unroll
        for (int ks = 0; ks < DH; ks += 8) {
            uint32_t af[4][4], bf[4][2];
            #pragma unroll
            for (int i = 0; i < 4; i++) {
                int r0 = (mb + i * 16 + g) * 68 + ks + ct;
                af[i][0] = Qs[r0];       af[i][2] = Qs[r0 + 4];
                af[i][1] = Qs[r0 + 544]; af[i][3] = Qs[r0 + 548];
            }
            #pragma unroll
            for (int j = 0; j < 4; j++) {
                int b0 = (nb + j * 8 + g) * 68 + ks + ct;
                bf[j][0] = tf32c(Kf[b0]); bf[j][1] = tf32c(Kf[b0 + 4]);
            }
            #pragma unroll
            for (int i = 0; i < 4; i++)
                #pragma unroll
                for (int j = 0; j < 4; j++) mma8(c[i][j], af[i], bf[j]);
        }
        // epilogue: p = exp(s)*inv -> score gmem (once) + Ps smem (tf32)
        #pragma unroll
        for (int i = 0; i < 4; i++) {
            int rloc = mb + i * 16 + g;
            float iv0 = invs[rloc], iv1 = invs[rloc + 8];
            int grow = q0 + rloc;
            #pragma unroll
            for (int j = 0; j < 4; j++) {
                int col = nb + j * 8 + ct * 2;
                int colg = n0 + col;
                float2 mk0 = *(const float2*)&mask[(size_t)grow * SS + colg];
                float p0 = fexp(fmaf(c[i][j][0], 0.125f, mk0.x)) * iv0;
                float p1 = fexp(fmaf(c[i][j][1], 0.125f, mk0.y)) * iv0;
                *(float2*)&score[sbase + (size_t)grow * SS + colg] = make_float2(p0, p1);
                Ps[rloc * 132 + col]     = tf32c(p0);
                Ps[rloc * 132 + col + 1] = tf32c(p1);
                float2 mk1 = *(const float2*)&mask[(size_t)(grow + 8) * SS + colg];
                float p2 = fexp(fmaf(c[i][j][2], 0.125f, mk1.x)) * iv1;
                float p3 = fexp(fmaf(c[i][j][3], 0.125f, mk1.y)) * iv1;
                *(float2*)&score[sbase + (size_t)(grow + 8) * SS + colg] = make_float2(p2, p3);
                Ps[(rloc + 8) * 132 + col]     = tf32c(p2);
                Ps[(rloc + 8) * 132 + col + 1] = tf32c(p3);
            }
        }
        CP_WAIT1;            // V_cur done (K_next may remain in flight)
        __syncthreads();     // Ps + Vs visible to all
        // PV: D += V^T x P^T over k=128
        #pragma unroll
        for (int ks = 0; ks < 128; ks += 8) {
            uint32_t af[2][4], bf[4][2];
            #pragma unroll
            for (int i = 0; i < 2; i++) {
                int a0 = (ks + ct) * 72 + pm + i * 16 + g;
                af[i][0] = tf32c(Vsf[a0]);       af[i][1] = tf32c(Vsf[a0 + 8]);
                af[i][2] = tf32c(Vsf[a0 + 288]); af[i][3] = tf32c(Vsf[a0 + 296]);
            }
            #pragma unroll
            for (int j = 0; j < 4; j++) {
                int b0 = (pn + j * 8 + g) * 132 + ks + ct;
                bf[j][0] = Ps[b0]; bf[j][1] = Ps[b0 + 4];
            }
            #pragma unroll
            for (int i = 0; i < 2; i++)
                #pragma unroll
                for (int j = 0; j < 4; j++) mma8(d[i][j], af[i], bf[j]);
        }
    }
    __syncthreads();
    // stage ctx^T -> smem (reuse Ps region as float, stride 68) for coalesced STG
    float* ctxs = (float*)Ps;
    #pragma unroll
    for (int i = 0; i < 2; i++) {
        int dh = pm + i * 16 + g;
        #pragma unroll
        for (int j = 0; j < 4; j++) {
            int qq = pn + j * 8 + ct * 2;
            ctxs[qq * 68 + dh]           = d[i][j][0];
            ctxs[(qq + 1) * 68 + dh]     = d[i][j][1];
            ctxs[qq * 68 + dh + 8]       = d[i][j][2];
            ctxs[(qq + 1) * 68 + dh + 8] = d[i][j][3];
        }
    }
    __syncthreads();
    float* C = g_ctx + (size_t)bh * SS * DH + (size_t)q0 * DH;
    #pragma unroll
    for (int it = 0; it < 8; it++) {
        int fi = tid + it * 256;
        int r = fi >> 4, c4 = (fi & 15) << 2;
        *(float4*)(C + (size_t)r * DH + c4) = *(float4*)&ctxs[r * 68 + c4];
    }
}

// ---------------------------------------------------------------------------
// K4: output projection. Same pipeline as k_qkv_proj, ctx gathered on load.
// ---------------------------------------------------------------------------
__global__ __launch_bounds__(256, 2) void k_oproj(
    const float* __restrict__ wo, const float* __restrict__ bo, float* __restrict__ out)
{
    __shared__ float As[2][2560];
    __shared__ float Bs[2][2560];
    int tid = threadIdx.x;
    int lane = tid & 31, wid = tid >> 5;
    int g = lane >> 2, ct = lane & 3;
    int mb = (wid >> 2) * 64, nb = (wid & 3) * 32;
    int m0 = blockIdx.y * 128, n0 = blockIdx.x * 128;

    uint32_t asb = (uint32_t)__cvta_generic_to_shared(&As[0][0]);
    uint32_t bsb = (uint32_t)__cvta_generic_to_shared(&Bs[0][0]);
    int rl = tid >> 2, cl = (tid & 3) << 2;

    // gather addressing for ctx rows rl and rl+64
    int m_a = m0 + rl,        b_a = m_a >> 11, s_a = m_a & (SS - 1);
    int m_b = m0 + rl + 64,   b_b = m_b >> 11, s_b = m_b & (SS - 1);

    float c[4][4][4];
    #pragma unroll
    for (int i = 0; i < 4; i++)
        #pragma unroll
        for (int j = 0; j < 4; j++)
            #pragma unroll
            for (int t = 0; t < 4; t++) c[i][j][t] = 0.0f;

    {
        int h = cl >> 6, dh = cl & 63;
        cpa16(asb + (0 * 2560 + rl * 20 + cl) * 4,
              g_ctx + ((size_t)(b_a * HH + h) * SS + s_a) * DH + dh);
        cpa16(asb + (0 * 2560 + (rl + 64) * 20 + cl) * 4,
              g_ctx + ((size_t)(b_b * HH + h) * SS + s_b) * DH + dh);
        cpa16(bsb + (0 * 2560 + rl * 20 + cl) * 4,        wo + (size_t)(n0 + rl) * DM + cl);
        cpa16(bsb + (0 * 2560 + (rl + 64) * 20 + cl) * 4, wo + (size_t)(n0 + rl + 64) * DM + cl);
    }
    CP_COMMIT;

    for (int k0 = 0, st = 0; k0 < DM; k0 += 16, st ^= 1) {
        CP_WAIT0;
        __syncthreads();
        if (k0 + 16 < DM) {
            int kn = k0 + 16, so = (st ^ 1) * 2560;
            int kidx = kn + cl;
            int h = kidx >> 6, dh = kidx & 63;
            cpa16(asb + (so + rl * 20 + cl) * 4,
                  g_ctx + ((size_t)(b_a * HH + h) * SS + s_a) * DH + dh);
            cpa16(asb + (so + (rl + 64) * 20 + cl) * 4,
                  g_ctx + ((size_t)(b_b * HH + h) * SS + s_b) * DH + dh);
            cpa16(bsb + (so + rl * 20 + cl) * 4,        wo + (size_t)(n0 + rl) * DM + kn + cl);
            cpa16(bsb + (so + (rl + 64) * 20 + cl) * 4, wo + (size_t)(n0 + rl + 64) * DM + kn + cl);
        }
        CP_COMMIT;
        const float* Af = &As[st][0];
        const float* Bf = &Bs[st][0];
        #pragma unroll
        for (int ks = 0; ks < 16; ks += 8) {
            uint32_t af[4][4], bf[4][2];
            #pragma unroll
            for (int i = 0; i < 4; i++) {
                int r0 = (mb + i * 16 + g) * 20 + ks + ct;
                af[i][0] = tf32c(Af[r0]);       af[i][2] = tf32c(Af[r0 + 4]);
                af[i][1] = tf32c(Af[r0 + 160]); af[i][3] = tf32c(Af[r0 + 164]);
            }
            #pragma unroll
            for (int j = 0; j < 4; j++) {
                int b0 = (nb + j * 8 + g) * 20 + ks + ct;
                bf[j][0] = tf32c(Bf[b0]); bf[j][1] = tf32c(Bf[b0 + 4]);
            }
            #pragma unroll
            for (int i = 0; i < 4; i++)
                #pragma unroll
                for (int j = 0; j < 4; j++) mma8(c[i][j], af[i], bf[j]);
        }
    }
    __syncthreads();
    #pragma unroll
    for (int i = 0; i < 4; i++) {
        int row = m0 + mb + i * 16 + g;
        #pragma unroll
        for (int j = 0; j < 4; j++) {
            int col = n0 + nb + j * 8 + ct * 2;
            float2 bi = *(const float2*)&bo[col];
            *(float2*)&out[(size_t)row * DM + col] =
                make_float2(c[i][j][0] + bi.x, c[i][j][1] + bi.y);
            *(float2*)&out[(size_t)(row + 8) * DM + col] =
                make_float2(c[i][j][2] + bi.x, c[i][j][3] + bi.y);
        }
    }
}

// ---------------------------------------------------------------------------
extern "C" void kernel_launch(void* const* d_in, const int* in_sizes, int n_in,
                              void* d_out, int out_size)
{
    const float* q    = (const float*)d_in[0];
    const float* k    = (const float*)d_in[1];
    const float* v    = (const float*)d_in[2];
    const float* mask = (const float*)d_in[3];
    const float* w_q  = (const float*)d_in[4];
    const float* b_q  = (const float*)d_in[5];
    const float* w_k  = (const float*)d_in[6];
    const float* b_k  = (const float*)d_in[7];
    const float* w_v  = (const float*)d_in[8];
    const float* b_v  = (const float*)d_in[9];
    const float* w_o  = (const float*)d_in[10];
    const float* b_o  = (const float*)d_in[11];

    float* out   = (float*)d_out;                        // x: [B,S,DM]
    float* score = out + (size_t)BB * SS * DM;           // score: [B,H,S,S]

    cudaFuncSetAttribute(k_attn, cudaFuncAttributeMaxDynamicSharedMemorySize, AT_BYTES);

    k_qkv_proj<<<dim3(DM/128, (BB*SS)/128, 3), 256>>>(q, k, v, w_q, w_k, w_v, b_q, b_k, b_v);
    k_attn<<<dim3(SS/128, BHT), 256, AT_BYTES>>>(mask, score);
    k_oproj<<<dim3(DM/128, (BB*SS)/128), 256>>>(w_o, b_o, out);
}